// round 1
// baseline (speedup 1.0000x reference)
#include <cuda_runtime.h>
#include <cstdint>

#define N_NODES 100000
#define D 128          // D_IN == D_OUT == 128
#define BM 64
#define BK 16

// 51.2 MB scratch for h = x @ W^T (static device global: allowed by harness rules)
__device__ float g_h[(size_t)N_NODES * D];

// ---------------------------------------------------------------------------
// GEMM: h[N,128] = x[N,128] @ W[128,128]^T   (fp32 SIMT, 64x128 block tile,
// 4x8 per-thread register tile, float4 smem paths)
// ---------------------------------------------------------------------------
__global__ __launch_bounds__(256) void gemm_xWt(const float* __restrict__ x,
                                                const float* __restrict__ W,
                                                int N) {
    __shared__ float As[BK][BM + 4];   // As[k][m]
    __shared__ float Bs[BK][D + 4];    // Bs[k][n] = W[n][k]

    const int tid  = threadIdx.x;
    const int row0 = blockIdx.x * BM;
    const int ty   = tid >> 4;   // 0..15 -> 4 rows each
    const int tx   = tid & 15;   // 0..15 -> 8 cols each

    float acc[4][8];
#pragma unroll
    for (int i = 0; i < 4; i++)
#pragma unroll
        for (int j = 0; j < 8; j++) acc[i][j] = 0.f;

    for (int k0 = 0; k0 < D; k0 += BK) {
        // --- load A tile: 64 rows x 16 k  (one float4 per thread) ---
        {
            int r  = tid >> 2;          // 0..63
            int kk = (tid & 3) * 4;     // 0,4,8,12
            int row = row0 + r;
            float4 v = make_float4(0.f, 0.f, 0.f, 0.f);
            if (row < N) v = *(const float4*)(x + (size_t)row * D + k0 + kk);
            As[kk + 0][r] = v.x; As[kk + 1][r] = v.y;
            As[kk + 2][r] = v.z; As[kk + 3][r] = v.w;
        }
        // --- load B tile: Bs[k][n] = W[n*128 + k0 + k]; two float4 per thread ---
        {
            int n = tid & 127;
            int g = tid >> 7;           // 0..1
#pragma unroll
            for (int gg = 0; gg < 2; gg++) {
                int kk = (g + gg * 2) * 4;   // covers 0,4,8,12 across threads
                float4 v = *(const float4*)(W + (size_t)n * D + k0 + kk);
                Bs[kk + 0][n] = v.x; Bs[kk + 1][n] = v.y;
                Bs[kk + 2][n] = v.z; Bs[kk + 3][n] = v.w;
            }
        }
        __syncthreads();

#pragma unroll
        for (int k = 0; k < BK; k++) {
            float4 a  = *(const float4*)&As[k][ty * 4];
            float4 b0 = *(const float4*)&Bs[k][tx * 8];
            float4 b1 = *(const float4*)&Bs[k][tx * 8 + 4];
            float av[4] = {a.x, a.y, a.z, a.w};
            float bv[8] = {b0.x, b0.y, b0.z, b0.w, b1.x, b1.y, b1.z, b1.w};
#pragma unroll
            for (int i = 0; i < 4; i++)
#pragma unroll
                for (int j = 0; j < 8; j++) acc[i][j] += av[i] * bv[j];
        }
        __syncthreads();
    }

#pragma unroll
    for (int i = 0; i < 4; i++) {
        int row = row0 + ty * 4 + i;
        if (row < N) {
            float4 o0 = make_float4(acc[i][0], acc[i][1], acc[i][2], acc[i][3]);
            float4 o1 = make_float4(acc[i][4], acc[i][5], acc[i][6], acc[i][7]);
            *(float4*)(g_h + (size_t)row * D + tx * 8)     = o0;
            *(float4*)(g_h + (size_t)row * D + tx * 8 + 4) = o1;
        }
    }
}

// ---------------------------------------------------------------------------
// Scatter: out[dst] += w_e * h[src].  Warp per edge; each lane owns 4 floats,
// one vectorized red.global.add.v4.f32 per lane (no return -> REDG path).
// ---------------------------------------------------------------------------
__global__ __launch_bounds__(256) void scatter_edges(const int* __restrict__ ei,
                                                     const float* __restrict__ ew,
                                                     float* __restrict__ out,
                                                     int E) {
    int warp = (blockIdx.x * blockDim.x + threadIdx.x) >> 5;
    int lane = threadIdx.x & 31;
    if (warp >= E) return;

    int   src = __ldg(ei + warp);
    int   dst = __ldg(ei + E + warp);
    float w   = __ldg(ew + warp);

    float4 v = *(const float4*)(g_h + (size_t)src * D + lane * 4);
    v.x *= w; v.y *= w; v.z *= w; v.w *= w;

    float* p = out + (size_t)dst * D + lane * 4;
    asm volatile("red.global.add.v4.f32 [%0], {%1, %2, %3, %4};"
                 :: "l"(p), "f"(v.x), "f"(v.y), "f"(v.z), "f"(v.w)
                 : "memory");
}

// ---------------------------------------------------------------------------
// Epilogue: out = relu(prelu(out + bias, a)), float4-vectorized in place.
// ---------------------------------------------------------------------------
__global__ __launch_bounds__(256) void epilogue(float* __restrict__ out,
                                                const float* __restrict__ bias,
                                                const float* __restrict__ pa,
                                                int n4) {
    int i = blockIdx.x * blockDim.x + threadIdx.x;
    if (i >= n4) return;
    float a = pa[0];
    float4 v = ((float4*)out)[i];
    int c = (i * 4) & (D - 1);
    float4 b = *(const float4*)(bias + c);
    v.x += b.x; v.y += b.y; v.z += b.z; v.w += b.w;
    v.x = fmaxf(v.x >= 0.f ? v.x : a * v.x, 0.f);
    v.y = fmaxf(v.y >= 0.f ? v.y : a * v.y, 0.f);
    v.z = fmaxf(v.z >= 0.f ? v.z : a * v.z, 0.f);
    v.w = fmaxf(v.w >= 0.f ? v.w : a * v.w, 0.f);
    ((float4*)out)[i] = v;
}

// ---------------------------------------------------------------------------
extern "C" void kernel_launch(void* const* d_in, const int* in_sizes, int n_in,
                              void* d_out, int out_size) {
    const float* x    = (const float*)d_in[0];
    const int*   ei   = (const int*)  d_in[1];
    const float* ew   = (const float*)d_in[2];
    const float* W    = (const float*)d_in[3];
    const float* bias = (const float*)d_in[4];
    const float* pa   = (const float*)d_in[5];
    float*       out  = (float*)d_out;

    const int N = in_sizes[0] / D;          // 100000
    const int E = in_sizes[2];              // 1600000

    // zero the accumulator (d_out is poisoned before timing)
    cudaMemsetAsync(d_out, 0, (size_t)out_size * sizeof(float));

    // h = x @ W^T
    gemm_xWt<<<(N + BM - 1) / BM, 256>>>(x, W, N);

    // edge scatter: one warp per edge -> E warps -> E/8 blocks of 256
    int warps_per_block = 256 / 32;
    int nblk = (E + warps_per_block - 1) / warps_per_block;
    scatter_edges<<<nblk, 256>>>(ei, ew, out, E);

    // bias + prelu + relu
    int n4 = out_size / 4;
    epilogue<<<(n4 + 255) / 256, 256>>>(out, bias, pa, n4);
}

// round 2
// speedup vs baseline: 1.4835x; 1.4835x over previous
#include <cuda_runtime.h>
#include <cstdint>

#define N_NODES 100000
#define E_MAX   1600000
#define D 128
#define BM 64
#define BK 16

typedef unsigned long long ull;

// Scratch (static device globals: allowed)
__device__ float g_h[(size_t)N_NODES * D];          // 51.2 MB: h = x @ W^T
__device__ int   g_cnt[N_NODES];                    // histogram
__device__ int   g_off[N_NODES + 1];                // CSR offsets (exclusive)
__device__ int   g_cur[N_NODES];                    // fill cursors
__device__ int   g_bsum[128];                       // block sums for scan
__device__ ull   g_epack[E_MAX];                    // packed {src, weight}

// ---------------------------------------------------------------------------
// GEMM: h[N,128] = x[N,128] @ W[128,128]^T  (unchanged from R1 — known correct)
// ---------------------------------------------------------------------------
__global__ __launch_bounds__(256) void gemm_xWt(const float* __restrict__ x,
                                                const float* __restrict__ W,
                                                int N) {
    __shared__ float As[BK][BM + 4];
    __shared__ float Bs[BK][D + 4];

    const int tid  = threadIdx.x;
    const int row0 = blockIdx.x * BM;
    const int ty   = tid >> 4;
    const int tx   = tid & 15;

    float acc[4][8];
#pragma unroll
    for (int i = 0; i < 4; i++)
#pragma unroll
        for (int j = 0; j < 8; j++) acc[i][j] = 0.f;

    for (int k0 = 0; k0 < D; k0 += BK) {
        {
            int r  = tid >> 2;
            int kk = (tid & 3) * 4;
            int row = row0 + r;
            float4 v = make_float4(0.f, 0.f, 0.f, 0.f);
            if (row < N) v = *(const float4*)(x + (size_t)row * D + k0 + kk);
            As[kk + 0][r] = v.x; As[kk + 1][r] = v.y;
            As[kk + 2][r] = v.z; As[kk + 3][r] = v.w;
        }
        {
            int n = tid & 127;
            int g = tid >> 7;
#pragma unroll
            for (int gg = 0; gg < 2; gg++) {
                int kk = (g + gg * 2) * 4;
                float4 v = *(const float4*)(W + (size_t)n * D + k0 + kk);
                Bs[kk + 0][n] = v.x; Bs[kk + 1][n] = v.y;
                Bs[kk + 2][n] = v.z; Bs[kk + 3][n] = v.w;
            }
        }
        __syncthreads();

#pragma unroll
        for (int k = 0; k < BK; k++) {
            float4 a  = *(const float4*)&As[k][ty * 4];
            float4 b0 = *(const float4*)&Bs[k][tx * 8];
            float4 b1 = *(const float4*)&Bs[k][tx * 8 + 4];
            float av[4] = {a.x, a.y, a.z, a.w};
            float bv[8] = {b0.x, b0.y, b0.z, b0.w, b1.x, b1.y, b1.z, b1.w};
#pragma unroll
            for (int i = 0; i < 4; i++)
#pragma unroll
                for (int j = 0; j < 8; j++) acc[i][j] += av[i] * bv[j];
        }
        __syncthreads();
    }

#pragma unroll
    for (int i = 0; i < 4; i++) {
        int row = row0 + ty * 4 + i;
        if (row < N) {
            float4 o0 = make_float4(acc[i][0], acc[i][1], acc[i][2], acc[i][3]);
            float4 o1 = make_float4(acc[i][4], acc[i][5], acc[i][6], acc[i][7]);
            *(float4*)(g_h + (size_t)row * D + tx * 8)     = o0;
            *(float4*)(g_h + (size_t)row * D + tx * 8 + 4) = o1;
        }
    }
}

// ---------------------------------------------------------------------------
// CSR build: zero -> histogram -> block scan -> scan of block sums -> fixup
// ---------------------------------------------------------------------------
__global__ void k_zero_cnt(int N) {
    int i = blockIdx.x * blockDim.x + threadIdx.x;
    if (i < N) g_cnt[i] = 0;
}

__global__ void k_hist(const int* __restrict__ ei, int E) {
    int e = blockIdx.x * blockDim.x + threadIdx.x;
    if (e >= E) return;
    atomicAdd(&g_cnt[ei[E + e]], 1);
}

// 1024-thread blocks; each scans 1024 elements of g_cnt -> exclusive into g_off
__global__ __launch_bounds__(1024) void k_scan1(int N) {
    __shared__ int wsum[32];
    int t = threadIdx.x;
    int i = blockIdx.x * 1024 + t;
    int lane = t & 31, wid = t >> 5;
    int v = (i < N) ? g_cnt[i] : 0;
    int x = v;
#pragma unroll
    for (int o = 1; o < 32; o <<= 1) {
        int y = __shfl_up_sync(0xffffffffu, x, o);
        if (lane >= o) x += y;
    }
    if (lane == 31) wsum[wid] = x;
    __syncthreads();
    if (wid == 0) {
        int s = wsum[lane];
#pragma unroll
        for (int o = 1; o < 32; o <<= 1) {
            int y = __shfl_up_sync(0xffffffffu, s, o);
            if (lane >= o) s += y;
        }
        wsum[lane] = s;
    }
    __syncthreads();
    int pre = (wid > 0) ? wsum[wid - 1] : 0;
    if (i < N) g_off[i] = pre + x - v;          // exclusive within block
    if (t == 1023) g_bsum[blockIdx.x] = pre + x; // block total
}

// single block: exclusive scan of (up to 128) block sums
__global__ __launch_bounds__(128) void k_scan2(int nb, int E) {
    __shared__ int s[128];
    int t = threadIdx.x;
    int v = (t < nb) ? g_bsum[t] : 0;
    s[t] = v;
    __syncthreads();
#pragma unroll
    for (int o = 1; o < 128; o <<= 1) {
        int add = (t >= o) ? s[t - o] : 0;
        __syncthreads();
        s[t] += add;
        __syncthreads();
    }
    if (t < nb) g_bsum[t] = s[t] - v;   // exclusive
    if (t == 0) g_off[N_NODES] = E;
}

__global__ void k_scan3(int N) {
    int i = blockIdx.x * blockDim.x + threadIdx.x;
    if (i >= N) return;
    int o = g_off[i] + g_bsum[i >> 10];
    g_off[i] = o;
    g_cur[i] = o;
}

__global__ void k_fill(const int* __restrict__ ei, const float* __restrict__ ew, int E) {
    int e = blockIdx.x * blockDim.x + threadIdx.x;
    if (e >= E) return;
    int src = ei[e];
    int dst = ei[E + e];
    int pos = atomicAdd(&g_cur[dst], 1);
    g_epack[pos] = ((ull)(unsigned)src << 32) | (ull)__float_as_uint(ew[e]);
}

// ---------------------------------------------------------------------------
// Gather + fused epilogue: warp per dst; out[dst] = relu(prelu(sum + bias))
// ---------------------------------------------------------------------------
__global__ __launch_bounds__(256) void gather_csr(const float* __restrict__ bias,
                                                  const float* __restrict__ pa,
                                                  float* __restrict__ out, int N) {
    int d    = (blockIdx.x * blockDim.x + threadIdx.x) >> 5;
    int lane = threadIdx.x & 31;
    if (d >= N) return;

    int beg = g_off[d];
    int end = g_off[d + 1];

    float4 a0 = make_float4(0.f, 0.f, 0.f, 0.f);
    float4 a1 = make_float4(0.f, 0.f, 0.f, 0.f);

    int i = beg;
    for (; i + 1 < end; i += 2) {
        ull p0 = __ldg(g_epack + i);
        ull p1 = __ldg(g_epack + i + 1);
        int   s0 = (int)(p0 >> 32);
        int   s1 = (int)(p1 >> 32);
        float w0 = __uint_as_float((unsigned)p0);
        float w1 = __uint_as_float((unsigned)p1);
        float4 v0 = *(const float4*)(g_h + (size_t)s0 * D + lane * 4);
        float4 v1 = *(const float4*)(g_h + (size_t)s1 * D + lane * 4);
        a0.x += w0 * v0.x; a0.y += w0 * v0.y; a0.z += w0 * v0.z; a0.w += w0 * v0.w;
        a1.x += w1 * v1.x; a1.y += w1 * v1.y; a1.z += w1 * v1.z; a1.w += w1 * v1.w;
    }
    if (i < end) {
        ull p0 = __ldg(g_epack + i);
        int   s0 = (int)(p0 >> 32);
        float w0 = __uint_as_float((unsigned)p0);
        float4 v0 = *(const float4*)(g_h + (size_t)s0 * D + lane * 4);
        a0.x += w0 * v0.x; a0.y += w0 * v0.y; a0.z += w0 * v0.z; a0.w += w0 * v0.w;
    }

    float  a = pa[0];
    float4 b = *(const float4*)(bias + lane * 4);
    float4 v;
    v.x = a0.x + a1.x + b.x;
    v.y = a0.y + a1.y + b.y;
    v.z = a0.z + a1.z + b.z;
    v.w = a0.w + a1.w + b.w;
    v.x = fmaxf(v.x >= 0.f ? v.x : a * v.x, 0.f);
    v.y = fmaxf(v.y >= 0.f ? v.y : a * v.y, 0.f);
    v.z = fmaxf(v.z >= 0.f ? v.z : a * v.z, 0.f);
    v.w = fmaxf(v.w >= 0.f ? v.w : a * v.w, 0.f);
    *(float4*)(out + (size_t)d * D + lane * 4) = v;
}

// ---------------------------------------------------------------------------
extern "C" void kernel_launch(void* const* d_in, const int* in_sizes, int n_in,
                              void* d_out, int out_size) {
    const float* x    = (const float*)d_in[0];
    const int*   ei   = (const int*)  d_in[1];
    const float* ew   = (const float*)d_in[2];
    const float* W    = (const float*)d_in[3];
    const float* bias = (const float*)d_in[4];
    const float* pa   = (const float*)d_in[5];
    float*       out  = (float*)d_out;

    const int N = in_sizes[0] / D;      // 100000
    const int E = in_sizes[2];          // 1600000
    const int nb = (N + 1023) / 1024;   // 98 scan blocks

    // CSR build
    k_zero_cnt<<<(N + 255) / 256, 256>>>(N);
    k_hist<<<(E + 255) / 256, 256>>>(ei, E);
    k_scan1<<<nb, 1024>>>(N);
    k_scan2<<<1, 128>>>(nb, E);
    k_scan3<<<(N + 255) / 256, 256>>>(N);
    k_fill<<<(E + 255) / 256, 256>>>(ei, ew, E);

    // h = x @ W^T (independent of CSR build; sequential on stream is fine)
    gemm_xWt<<<(N + BM - 1) / BM, 256>>>(x, W, N);

    // gather + bias + prelu + relu (writes every output row; no memset needed)
    gather_csr<<<(N * 32 + 255) / 256, 256>>>(bias, pa, out, N);
}

// round 3
// speedup vs baseline: 1.7051x; 1.1494x over previous
#include <cuda_runtime.h>
#include <cstdint>

#define N_NODES 100000
#define E_MAX   1600000
#define D 128

typedef unsigned long long ull;

// Scratch (static device globals: allowed)
__device__ float g_h[(size_t)N_NODES * D];          // 51.2 MB: h = x @ W^T
__device__ int   g_cnt[N_NODES];                    // histogram
__device__ int   g_off[N_NODES + 1];                // CSR offsets (exclusive)
__device__ int   g_cur[N_NODES];                    // fill cursors
__device__ int   g_bsum[128];                       // block sums for scan
__device__ ull   g_epack[E_MAX];                    // packed {src, weight}

// ---------------------------------------------------------------------------
// GEMM: h[N,128] = x[N,128] @ W[128,128]^T
// 128x128x8 block tile, 8x8 register tile, 256 threads.
// ---------------------------------------------------------------------------
#define BM 128
#define BN 128
#define BK 8

__global__ __launch_bounds__(256) void gemm_xWt(const float* __restrict__ x,
                                                const float* __restrict__ W,
                                                int N) {
    __shared__ float As[BK][BM + 4];   // As[k][m]
    __shared__ float Bs[BK][BN + 4];   // Bs[k][n] = W[n][k]

    const int tid  = threadIdx.x;
    const int row0 = blockIdx.x * BM;
    const int tx   = tid & 15;         // 0..15 -> n-frag
    const int ty   = tid >> 4;         // 0..15 -> m-frag

    // load indices: each thread loads one float4 per tile per operand
    const int lr = tid >> 1;           // 0..127 row within tile
    const int lk = (tid & 1) * 4;      // 0 or 4

    float acc[8][8];
#pragma unroll
    for (int i = 0; i < 8; i++)
#pragma unroll
        for (int j = 0; j < 8; j++) acc[i][j] = 0.f;

    for (int k0 = 0; k0 < D; k0 += BK) {
        // A tile: x[row0+lr][k0+lk..+3] -> As[k][m]
        {
            int row = row0 + lr;
            float4 v = make_float4(0.f, 0.f, 0.f, 0.f);
            if (row < N) v = *(const float4*)(x + (size_t)row * D + k0 + lk);
            As[lk + 0][lr] = v.x; As[lk + 1][lr] = v.y;
            As[lk + 2][lr] = v.z; As[lk + 3][lr] = v.w;
        }
        // B tile: W[lr][k0+lk..+3] -> Bs[k][n]
        {
            float4 v = *(const float4*)(W + (size_t)lr * D + k0 + lk);
            Bs[lk + 0][lr] = v.x; Bs[lk + 1][lr] = v.y;
            Bs[lk + 2][lr] = v.z; Bs[lk + 3][lr] = v.w;
        }
        __syncthreads();

#pragma unroll
        for (int k = 0; k < BK; k++) {
            float4 a0 = *(const float4*)&As[k][ty * 8];
            float4 a1 = *(const float4*)&As[k][ty * 8 + 4];
            float4 b0 = *(const float4*)&Bs[k][tx * 8];
            float4 b1 = *(const float4*)&Bs[k][tx * 8 + 4];
            float av[8] = {a0.x, a0.y, a0.z, a0.w, a1.x, a1.y, a1.z, a1.w};
            float bv[8] = {b0.x, b0.y, b0.z, b0.w, b1.x, b1.y, b1.z, b1.w};
#pragma unroll
            for (int i = 0; i < 8; i++)
#pragma unroll
                for (int j = 0; j < 8; j++) acc[i][j] += av[i] * bv[j];
        }
        __syncthreads();
    }

#pragma unroll
    for (int i = 0; i < 8; i++) {
        int row = row0 + ty * 8 + i;
        if (row < N) {
            float4 o0 = make_float4(acc[i][0], acc[i][1], acc[i][2], acc[i][3]);
            float4 o1 = make_float4(acc[i][4], acc[i][5], acc[i][6], acc[i][7]);
            *(float4*)(g_h + (size_t)row * D + tx * 8)     = o0;
            *(float4*)(g_h + (size_t)row * D + tx * 8 + 4) = o1;
        }
    }
}

// ---------------------------------------------------------------------------
// CSR build: zero -> histogram -> block scan -> scan of block sums -> fixup
// ---------------------------------------------------------------------------
__global__ void k_zero_cnt(int N) {
    int i = blockIdx.x * blockDim.x + threadIdx.x;
    if (i < N) g_cnt[i] = 0;
}

__global__ void k_hist(const int* __restrict__ ei, int E) {
    int e = blockIdx.x * blockDim.x + threadIdx.x;
    if (e >= E) return;
    atomicAdd(&g_cnt[__ldg(ei + E + e)], 1);
}

__global__ __launch_bounds__(1024) void k_scan1(int N) {
    __shared__ int wsum[32];
    int t = threadIdx.x;
    int i = blockIdx.x * 1024 + t;
    int lane = t & 31, wid = t >> 5;
    int v = (i < N) ? g_cnt[i] : 0;
    int x = v;
#pragma unroll
    for (int o = 1; o < 32; o <<= 1) {
        int y = __shfl_up_sync(0xffffffffu, x, o);
        if (lane >= o) x += y;
    }
    if (lane == 31) wsum[wid] = x;
    __syncthreads();
    if (wid == 0) {
        int s = wsum[lane];
#pragma unroll
        for (int o = 1; o < 32; o <<= 1) {
            int y = __shfl_up_sync(0xffffffffu, s, o);
            if (lane >= o) s += y;
        }
        wsum[lane] = s;
    }
    __syncthreads();
    int pre = (wid > 0) ? wsum[wid - 1] : 0;
    if (i < N) g_off[i] = pre + x - v;
    if (t == 1023) g_bsum[blockIdx.x] = pre + x;
}

__global__ __launch_bounds__(128) void k_scan2(int nb, int E) {
    __shared__ int s[128];
    int t = threadIdx.x;
    int v = (t < nb) ? g_bsum[t] : 0;
    s[t] = v;
    __syncthreads();
#pragma unroll
    for (int o = 1; o < 128; o <<= 1) {
        int add = (t >= o) ? s[t - o] : 0;
        __syncthreads();
        s[t] += add;
        __syncthreads();
    }
    if (t < nb) g_bsum[t] = s[t] - v;
    if (t == 0) g_off[N_NODES] = E;
}

__global__ void k_scan3(int N) {
    int i = blockIdx.x * blockDim.x + threadIdx.x;
    if (i >= N) return;
    int o = g_off[i] + g_bsum[i >> 10];
    g_off[i] = o;
    g_cur[i] = o;
}

__global__ void k_fill(const int* __restrict__ ei, const float* __restrict__ ew, int E) {
    int e = blockIdx.x * blockDim.x + threadIdx.x;
    if (e >= E) return;
    int src = __ldg(ei + e);
    int dst = __ldg(ei + E + e);
    int pos = atomicAdd(&g_cur[dst], 1);
    g_epack[pos] = ((ull)(unsigned)src << 32) | (ull)__float_as_uint(__ldg(ew + e));
}

// ---------------------------------------------------------------------------
// Gather + fused epilogue: warp per dst; 4-way unroll for MLP.
// ---------------------------------------------------------------------------
__global__ __launch_bounds__(256) void gather_csr(const float* __restrict__ bias,
                                                  const float* __restrict__ pa,
                                                  float* __restrict__ out, int N) {
    int d    = (blockIdx.x * blockDim.x + threadIdx.x) >> 5;
    int lane = threadIdx.x & 31;
    if (d >= N) return;

    int beg = g_off[d];
    int end = g_off[d + 1];

    float4 a0 = make_float4(0.f, 0.f, 0.f, 0.f);
    float4 a1 = make_float4(0.f, 0.f, 0.f, 0.f);
    float4 a2 = make_float4(0.f, 0.f, 0.f, 0.f);
    float4 a3 = make_float4(0.f, 0.f, 0.f, 0.f);

    int i = beg;
    for (; i + 3 < end; i += 4) {
        ull p0 = __ldg(g_epack + i);
        ull p1 = __ldg(g_epack + i + 1);
        ull p2 = __ldg(g_epack + i + 2);
        ull p3 = __ldg(g_epack + i + 3);
        float4 v0 = *(const float4*)(g_h + (size_t)(p0 >> 32) * D + lane * 4);
        float4 v1 = *(const float4*)(g_h + (size_t)(p1 >> 32) * D + lane * 4);
        float4 v2 = *(const float4*)(g_h + (size_t)(p2 >> 32) * D + lane * 4);
        float4 v3 = *(const float4*)(g_h + (size_t)(p3 >> 32) * D + lane * 4);
        float w0 = __uint_as_float((unsigned)p0);
        float w1 = __uint_as_float((unsigned)p1);
        float w2 = __uint_as_float((unsigned)p2);
        float w3 = __uint_as_float((unsigned)p3);
        a0.x += w0 * v0.x; a0.y += w0 * v0.y; a0.z += w0 * v0.z; a0.w += w0 * v0.w;
        a1.x += w1 * v1.x; a1.y += w1 * v1.y; a1.z += w1 * v1.z; a1.w += w1 * v1.w;
        a2.x += w2 * v2.x; a2.y += w2 * v2.y; a2.z += w2 * v2.z; a2.w += w2 * v2.w;
        a3.x += w3 * v3.x; a3.y += w3 * v3.y; a3.z += w3 * v3.z; a3.w += w3 * v3.w;
    }
    for (; i < end; i++) {
        ull p0 = __ldg(g_epack + i);
        float w0 = __uint_as_float((unsigned)p0);
        float4 v0 = *(const float4*)(g_h + (size_t)(p0 >> 32) * D + lane * 4);
        a0.x += w0 * v0.x; a0.y += w0 * v0.y; a0.z += w0 * v0.z; a0.w += w0 * v0.w;
    }

    float  a = pa[0];
    float4 b = *(const float4*)(bias + lane * 4);
    float4 v;
    v.x = a0.x + a1.x + a2.x + a3.x + b.x;
    v.y = a0.y + a1.y + a2.y + a3.y + b.y;
    v.z = a0.z + a1.z + a2.z + a3.z + b.z;
    v.w = a0.w + a1.w + a2.w + a3.w + b.w;
    v.x = fmaxf(v.x >= 0.f ? v.x : a * v.x, 0.f);
    v.y = fmaxf(v.y >= 0.f ? v.y : a * v.y, 0.f);
    v.z = fmaxf(v.z >= 0.f ? v.z : a * v.z, 0.f);
    v.w = fmaxf(v.w >= 0.f ? v.w : a * v.w, 0.f);
    *(float4*)(out + (size_t)d * D + lane * 4) = v;
}

// ---------------------------------------------------------------------------
extern "C" void kernel_launch(void* const* d_in, const int* in_sizes, int n_in,
                              void* d_out, int out_size) {
    const float* x    = (const float*)d_in[0];
    const int*   ei   = (const int*)  d_in[1];
    const float* ew   = (const float*)d_in[2];
    const float* W    = (const float*)d_in[3];
    const float* bias = (const float*)d_in[4];
    const float* pa   = (const float*)d_in[5];
    float*       out  = (float*)d_out;

    const int N = in_sizes[0] / D;      // 100000
    const int E = in_sizes[2];          // 1600000
    const int nb = (N + 1023) / 1024;

    // CSR build
    k_zero_cnt<<<(N + 255) / 256, 256>>>(N);
    k_hist<<<(E + 255) / 256, 256>>>(ei, E);
    k_scan1<<<nb, 1024>>>(N);
    k_scan2<<<1, 128>>>(nb, E);
    k_scan3<<<(N + 255) / 256, 256>>>(N);
    k_fill<<<(E + 255) / 256, 256>>>(ei, ew, E);

    // h = x @ W^T
    gemm_xWt<<<(N + BM - 1) / BM, 256>>>(x, W, N);

    // gather + bias + prelu + relu
    gather_csr<<<(N * 32 + 255) / 256, 256>>>(bias, pa, out, N);
}

// round 5
// speedup vs baseline: 2.3815x; 1.3967x over previous
#include <cuda_runtime.h>
#include <cstdint>

#define N_NODES 100000
#define E_MAX   1600000
#define D 128

typedef unsigned long long ull;

// Scratch (static device globals: allowed)
__device__ float g_h[(size_t)N_NODES * D];          // 51.2 MB: h = x @ W^T
__device__ int   g_cnt[N_NODES];
__device__ int   g_off[N_NODES + 1];
__device__ int   g_cur[N_NODES];
__device__ int   g_bsum[128];
__device__ ull   g_epack[E_MAX];

__device__ __forceinline__ uint32_t f2tf32(float f) {
    uint32_t r;
    asm("cvt.rna.tf32.f32 %0, %1;" : "=r"(r) : "f"(f));
    return r;
}

// ---------------------------------------------------------------------------
// GEMM via mma.sync tf32 (HMMA path, valid on compute_103 base target):
// h[N,128] = x[N,128] @ W[128,128]^T.
// CTA: 128 rows x 128 cols, K=128 smem-resident. 8 warps, each 32x64.
// ---------------------------------------------------------------------------
#define PADK 132   // 128 + 4 pad: (132*n + j) mod 32 = (4n + j) mod 32 -> conflict-free
#define GEMM_SMEM (2 * 128 * PADK * 4)

__global__ __launch_bounds__(256) void gemm_mma(const float* __restrict__ x,
                                                const float* __restrict__ W,
                                                int N) {
    extern __shared__ uint32_t smA[];          // As[128][PADK] tf32 bits
    uint32_t* smB = smA + 128 * PADK;          // Bs[128][PADK] = W rows

    const int tid  = threadIdx.x;
    const int row0 = blockIdx.x * 128;

    // ---- load + convert to tf32 (float4-coalesced) ----
#pragma unroll
    for (int it = 0; it < 16; it++) {
        int idx = it * 256 + tid;
        int r   = idx >> 5;        // 0..127
        int c4  = idx & 31;        // float4 chunk
        float4 va = make_float4(0.f, 0.f, 0.f, 0.f);
        if (row0 + r < N) va = *(const float4*)(x + (size_t)(row0 + r) * D + c4 * 4);
        uint4 ta = make_uint4(f2tf32(va.x), f2tf32(va.y), f2tf32(va.z), f2tf32(va.w));
        *(uint4*)(smA + r * PADK + c4 * 4) = ta;

        float4 vb = *(const float4*)(W + (size_t)r * D + c4 * 4);
        uint4 tb = make_uint4(f2tf32(vb.x), f2tf32(vb.y), f2tf32(vb.z), f2tf32(vb.w));
        *(uint4*)(smB + r * PADK + c4 * 4) = tb;
    }
    __syncthreads();

    const int wid  = tid >> 5, lane = tid & 31;
    const int wm   = (wid >> 1) * 32;     // warp row offset (0,32,64,96)
    const int wn   = (wid & 1) * 64;      // warp col offset (0,64)
    const int gq   = lane >> 2;           // group id 0..7
    const int tig  = lane & 3;            // thread in group

    float acc[2][8][4];
#pragma unroll
    for (int mt = 0; mt < 2; mt++)
#pragma unroll
        for (int nt = 0; nt < 8; nt++)
#pragma unroll
            for (int c = 0; c < 4; c++) acc[mt][nt][c] = 0.f;

#pragma unroll
    for (int k8 = 0; k8 < 16; k8++) {
        const int k = k8 * 8;
        uint32_t a[2][4];
#pragma unroll
        for (int mt = 0; mt < 2; mt++) {
            int rb = wm + mt * 16;
            a[mt][0] = smA[(rb + gq)     * PADK + k + tig];
            a[mt][1] = smA[(rb + 8 + gq) * PADK + k + tig];
            a[mt][2] = smA[(rb + gq)     * PADK + k + 4 + tig];
            a[mt][3] = smA[(rb + 8 + gq) * PADK + k + 4 + tig];
        }
        uint32_t b[8][2];
#pragma unroll
        for (int nt = 0; nt < 8; nt++) {
            int n = wn + nt * 8 + gq;
            b[nt][0] = smB[n * PADK + k + tig];
            b[nt][1] = smB[n * PADK + k + 4 + tig];
        }
#pragma unroll
        for (int mt = 0; mt < 2; mt++)
#pragma unroll
            for (int nt = 0; nt < 8; nt++) {
                asm volatile(
                    "mma.sync.aligned.m16n8k8.row.col.f32.tf32.tf32.f32 "
                    "{%0,%1,%2,%3}, {%4,%5,%6,%7}, {%8,%9}, {%0,%1,%2,%3};"
                    : "+f"(acc[mt][nt][0]), "+f"(acc[mt][nt][1]),
                      "+f"(acc[mt][nt][2]), "+f"(acc[mt][nt][3])
                    : "r"(a[mt][0]), "r"(a[mt][1]), "r"(a[mt][2]), "r"(a[mt][3]),
                      "r"(b[nt][0]), "r"(b[nt][1]));
            }
    }

    // ---- store: c0/c1 adjacent cols -> float2; rows gq and gq+8 ----
#pragma unroll
    for (int mt = 0; mt < 2; mt++) {
        int r1 = row0 + wm + mt * 16 + gq;
        int r2 = r1 + 8;
#pragma unroll
        for (int nt = 0; nt < 8; nt++) {
            int c = wn + nt * 8 + tig * 2;
            if (r1 < N)
                *(float2*)(g_h + (size_t)r1 * D + c) = make_float2(acc[mt][nt][0], acc[mt][nt][1]);
            if (r2 < N)
                *(float2*)(g_h + (size_t)r2 * D + c) = make_float2(acc[mt][nt][2], acc[mt][nt][3]);
        }
    }
}

// ---------------------------------------------------------------------------
// CSR build (unchanged, verified)
// ---------------------------------------------------------------------------
__global__ void k_zero_cnt(int N) {
    int i = blockIdx.x * blockDim.x + threadIdx.x;
    if (i < N) g_cnt[i] = 0;
}

__global__ void k_hist(const int* __restrict__ ei, int E) {
    int e = blockIdx.x * blockDim.x + threadIdx.x;
    if (e >= E) return;
    atomicAdd(&g_cnt[__ldg(ei + E + e)], 1);
}

__global__ __launch_bounds__(1024) void k_scan1(int N) {
    __shared__ int wsum[32];
    int t = threadIdx.x;
    int i = blockIdx.x * 1024 + t;
    int lane = t & 31, wid = t >> 5;
    int v = (i < N) ? g_cnt[i] : 0;
    int x = v;
#pragma unroll
    for (int o = 1; o < 32; o <<= 1) {
        int y = __shfl_up_sync(0xffffffffu, x, o);
        if (lane >= o) x += y;
    }
    if (lane == 31) wsum[wid] = x;
    __syncthreads();
    if (wid == 0) {
        int s = wsum[lane];
#pragma unroll
        for (int o = 1; o < 32; o <<= 1) {
            int y = __shfl_up_sync(0xffffffffu, s, o);
            if (lane >= o) s += y;
        }
        wsum[lane] = s;
    }
    __syncthreads();
    int pre = (wid > 0) ? wsum[wid - 1] : 0;
    if (i < N) g_off[i] = pre + x - v;
    if (t == 1023) g_bsum[blockIdx.x] = pre + x;
}

__global__ __launch_bounds__(128) void k_scan2(int nb, int E) {
    __shared__ int s[128];
    int t = threadIdx.x;
    int v = (t < nb) ? g_bsum[t] : 0;
    s[t] = v;
    __syncthreads();
#pragma unroll
    for (int o = 1; o < 128; o <<= 1) {
        int add = (t >= o) ? s[t - o] : 0;
        __syncthreads();
        s[t] += add;
        __syncthreads();
    }
    if (t < nb) g_bsum[t] = s[t] - v;
    if (t == 0) g_off[N_NODES] = E;
}

__global__ void k_scan3(int N) {
    int i = blockIdx.x * blockDim.x + threadIdx.x;
    if (i >= N) return;
    int o = g_off[i] + g_bsum[i >> 10];
    g_off[i] = o;
    g_cur[i] = o;
}

__global__ void k_fill(const int* __restrict__ ei, const float* __restrict__ ew, int E) {
    int e = blockIdx.x * blockDim.x + threadIdx.x;
    if (e >= E) return;
    int src = __ldg(ei + e);
    int dst = __ldg(ei + E + e);
    int pos = atomicAdd(&g_cur[dst], 1);
    g_epack[pos] = ((ull)(unsigned)src << 32) | (ull)__float_as_uint(__ldg(ew + e));
}

// ---------------------------------------------------------------------------
// Gather + fused epilogue (unchanged, verified)
// ---------------------------------------------------------------------------
__global__ __launch_bounds__(256) void gather_csr(const float* __restrict__ bias,
                                                  const float* __restrict__ pa,
                                                  float* __restrict__ out, int N) {
    int d    = (blockIdx.x * blockDim.x + threadIdx.x) >> 5;
    int lane = threadIdx.x & 31;
    if (d >= N) return;

    int beg = g_off[d];
    int end = g_off[d + 1];

    float4 a0 = make_float4(0.f, 0.f, 0.f, 0.f);
    float4 a1 = make_float4(0.f, 0.f, 0.f, 0.f);
    float4 a2 = make_float4(0.f, 0.f, 0.f, 0.f);
    float4 a3 = make_float4(0.f, 0.f, 0.f, 0.f);

    int i = beg;
    for (; i + 3 < end; i += 4) {
        ull p0 = __ldg(g_epack + i);
        ull p1 = __ldg(g_epack + i + 1);
        ull p2 = __ldg(g_epack + i + 2);
        ull p3 = __ldg(g_epack + i + 3);
        float4 v0 = *(const float4*)(g_h + (size_t)(p0 >> 32) * D + lane * 4);
        float4 v1 = *(const float4*)(g_h + (size_t)(p1 >> 32) * D + lane * 4);
        float4 v2 = *(const float4*)(g_h + (size_t)(p2 >> 32) * D + lane * 4);
        float4 v3 = *(const float4*)(g_h + (size_t)(p3 >> 32) * D + lane * 4);
        float w0 = __uint_as_float((unsigned)p0);
        float w1 = __uint_as_float((unsigned)p1);
        float w2 = __uint_as_float((unsigned)p2);
        float w3 = __uint_as_float((unsigned)p3);
        a0.x += w0 * v0.x; a0.y += w0 * v0.y; a0.z += w0 * v0.z; a0.w += w0 * v0.w;
        a1.x += w1 * v1.x; a1.y += w1 * v1.y; a1.z += w1 * v1.z; a1.w += w1 * v1.w;
        a2.x += w2 * v2.x; a2.y += w2 * v2.y; a2.z += w2 * v2.z; a2.w += w2 * v2.w;
        a3.x += w3 * v3.x; a3.y += w3 * v3.y; a3.z += w3 * v3.z; a3.w += w3 * v3.w;
    }
    for (; i < end; i++) {
        ull p0 = __ldg(g_epack + i);
        float w0 = __uint_as_float((unsigned)p0);
        float4 v0 = *(const float4*)(g_h + (size_t)(p0 >> 32) * D + lane * 4);
        a0.x += w0 * v0.x; a0.y += w0 * v0.y; a0.z += w0 * v0.z; a0.w += w0 * v0.w;
    }

    float  a = pa[0];
    float4 b = *(const float4*)(bias + lane * 4);
    float4 v;
    v.x = a0.x + a1.x + a2.x + a3.x + b.x;
    v.y = a0.y + a1.y + a2.y + a3.y + b.y;
    v.z = a0.z + a1.z + a2.z + a3.z + b.z;
    v.w = a0.w + a1.w + a2.w + a3.w + b.w;
    v.x = fmaxf(v.x >= 0.f ? v.x : a * v.x, 0.f);
    v.y = fmaxf(v.y >= 0.f ? v.y : a * v.y, 0.f);
    v.z = fmaxf(v.z >= 0.f ? v.z : a * v.z, 0.f);
    v.w = fmaxf(v.w >= 0.f ? v.w : a * v.w, 0.f);
    *(float4*)(out + (size_t)d * D + lane * 4) = v;
}

// ---------------------------------------------------------------------------
extern "C" void kernel_launch(void* const* d_in, const int* in_sizes, int n_in,
                              void* d_out, int out_size) {
    const float* x    = (const float*)d_in[0];
    const int*   ei   = (const int*)  d_in[1];
    const float* ew   = (const float*)d_in[2];
    const float* W    = (const float*)d_in[3];
    const float* bias = (const float*)d_in[4];
    const float* pa   = (const float*)d_in[5];
    float*       out  = (float*)d_out;

    const int N = in_sizes[0] / D;      // 100000
    const int E = in_sizes[2];          // 1600000
    const int nb = (N + 1023) / 1024;

    // CSR build
    k_zero_cnt<<<(N + 255) / 256, 256>>>(N);
    k_hist<<<(E + 255) / 256, 256>>>(ei, E);
    k_scan1<<<nb, 1024>>>(N);
    k_scan2<<<1, 128>>>(nb, E);
    k_scan3<<<(N + 255) / 256, 256>>>(N);
    k_fill<<<(E + 255) / 256, 256>>>(ei, ew, E);

    // h = x @ W^T on tensor cores (mma.sync tf32)
    cudaFuncSetAttribute(gemm_mma, cudaFuncAttributeMaxDynamicSharedMemorySize, GEMM_SMEM);
    gemm_mma<<<(N + 127) / 128, 256, GEMM_SMEM>>>(x, W, N);

    // gather + bias + prelu + relu
    gather_csr<<<(N * 32 + 255) / 256, 256>>>(bias, pa, out, N);
}

// round 6
// speedup vs baseline: 2.5121x; 1.0548x over previous
#include <cuda_runtime.h>
#include <cuda_fp16.h>
#include <cstdint>

#define N_NODES 100000
#define E_MAX   1600000
#define D 128

typedef unsigned long long ull;

// Scratch (static device globals: allowed)
__device__ __half g_hh[(size_t)N_NODES * D];        // 25.6 MB: h = x @ W^T (fp16)
__device__ int   g_cnt[N_NODES];
__device__ int   g_off[N_NODES + 1];
__device__ int   g_cur[N_NODES];
__device__ int   g_bsum[128];
__device__ ull   g_epack[E_MAX];

__device__ __forceinline__ uint32_t f2tf32(float f) {
    uint32_t r;
    asm("cvt.rna.tf32.f32 %0, %1;" : "=r"(r) : "f"(f));
    return r;
}

// ---------------------------------------------------------------------------
// GEMM via mma.sync tf32: h[N,128] = x[N,128] @ W[128,128]^T, fp16 output.
// CTA: 128x128, K=128 smem-resident. 8 warps, each 32x64.
// ---------------------------------------------------------------------------
#define PADK 132   // (132n + j) mod 32 = (4n + j) mod 32 -> conflict-free
#define GEMM_SMEM (2 * 128 * PADK * 4)

__global__ __launch_bounds__(256) void gemm_mma(const float* __restrict__ x,
                                                const float* __restrict__ W,
                                                int N) {
    extern __shared__ uint32_t smA[];          // As[128][PADK] tf32 bits
    uint32_t* smB = smA + 128 * PADK;          // Bs[128][PADK] = W rows

    const int tid  = threadIdx.x;
    const int row0 = blockIdx.x * 128;

#pragma unroll
    for (int it = 0; it < 16; it++) {
        int idx = it * 256 + tid;
        int r   = idx >> 5;
        int c4  = idx & 31;
        float4 va = make_float4(0.f, 0.f, 0.f, 0.f);
        if (row0 + r < N) va = *(const float4*)(x + (size_t)(row0 + r) * D + c4 * 4);
        uint4 ta = make_uint4(f2tf32(va.x), f2tf32(va.y), f2tf32(va.z), f2tf32(va.w));
        *(uint4*)(smA + r * PADK + c4 * 4) = ta;

        float4 vb = *(const float4*)(W + (size_t)r * D + c4 * 4);
        uint4 tb = make_uint4(f2tf32(vb.x), f2tf32(vb.y), f2tf32(vb.z), f2tf32(vb.w));
        *(uint4*)(smB + r * PADK + c4 * 4) = tb;
    }
    __syncthreads();

    const int wid  = tid >> 5, lane = tid & 31;
    const int wm   = (wid >> 1) * 32;
    const int wn   = (wid & 1) * 64;
    const int gq   = lane >> 2;
    const int tig  = lane & 3;

    float acc[2][8][4];
#pragma unroll
    for (int mt = 0; mt < 2; mt++)
#pragma unroll
        for (int nt = 0; nt < 8; nt++)
#pragma unroll
            for (int c = 0; c < 4; c++) acc[mt][nt][c] = 0.f;

#pragma unroll
    for (int k8 = 0; k8 < 16; k8++) {
        const int k = k8 * 8;
        uint32_t a[2][4];
#pragma unroll
        for (int mt = 0; mt < 2; mt++) {
            int rb = wm + mt * 16;
            a[mt][0] = smA[(rb + gq)     * PADK + k + tig];
            a[mt][1] = smA[(rb + 8 + gq) * PADK + k + tig];
            a[mt][2] = smA[(rb + gq)     * PADK + k + 4 + tig];
            a[mt][3] = smA[(rb + 8 + gq) * PADK + k + 4 + tig];
        }
        uint32_t b[8][2];
#pragma unroll
        for (int nt = 0; nt < 8; nt++) {
            int n = wn + nt * 8 + gq;
            b[nt][0] = smB[n * PADK + k + tig];
            b[nt][1] = smB[n * PADK + k + 4 + tig];
        }
#pragma unroll
        for (int mt = 0; mt < 2; mt++)
#pragma unroll
            for (int nt = 0; nt < 8; nt++) {
                asm volatile(
                    "mma.sync.aligned.m16n8k8.row.col.f32.tf32.tf32.f32 "
                    "{%0,%1,%2,%3}, {%4,%5,%6,%7}, {%8,%9}, {%0,%1,%2,%3};"
                    : "+f"(acc[mt][nt][0]), "+f"(acc[mt][nt][1]),
                      "+f"(acc[mt][nt][2]), "+f"(acc[mt][nt][3])
                    : "r"(a[mt][0]), "r"(a[mt][1]), "r"(a[mt][2]), "r"(a[mt][3]),
                      "r"(b[nt][0]), "r"(b[nt][1]));
            }
    }

    // store fp16: (c0,c1) adjacent -> half2
#pragma unroll
    for (int mt = 0; mt < 2; mt++) {
        int r1 = row0 + wm + mt * 16 + gq;
        int r2 = r1 + 8;
#pragma unroll
        for (int nt = 0; nt < 8; nt++) {
            int c = wn + nt * 8 + tig * 2;
            if (r1 < N)
                *(__half2*)(g_hh + (size_t)r1 * D + c) =
                    __floats2half2_rn(acc[mt][nt][0], acc[mt][nt][1]);
            if (r2 < N)
                *(__half2*)(g_hh + (size_t)r2 * D + c) =
                    __floats2half2_rn(acc[mt][nt][2], acc[mt][nt][3]);
        }
    }
}

// ---------------------------------------------------------------------------
// CSR build
// ---------------------------------------------------------------------------
__global__ void k_hist(const int* __restrict__ ei, int E) {
    int e = blockIdx.x * blockDim.x + threadIdx.x;
    if (e >= E) return;
    atomicAdd(&g_cnt[__ldg(ei + E + e)], 1);
}

__global__ __launch_bounds__(1024) void k_scan1(int N) {
    __shared__ int wsum[32];
    int t = threadIdx.x;
    int i = blockIdx.x * 1024 + t;
    int lane = t & 31, wid = t >> 5;
    int v = (i < N) ? g_cnt[i] : 0;
    int x = v;
#pragma unroll
    for (int o = 1; o < 32; o <<= 1) {
        int y = __shfl_up_sync(0xffffffffu, x, o);
        if (lane >= o) x += y;
    }
    if (lane == 31) wsum[wid] = x;
    __syncthreads();
    if (wid == 0) {
        int s = wsum[lane];
#pragma unroll
        for (int o = 1; o < 32; o <<= 1) {
            int y = __shfl_up_sync(0xffffffffu, s, o);
            if (lane >= o) s += y;
        }
        wsum[lane] = s;
    }
    __syncthreads();
    int pre = (wid > 0) ? wsum[wid - 1] : 0;
    if (i < N) g_off[i] = pre + x - v;
    if (t == 1023) g_bsum[blockIdx.x] = pre + x;
}

// Merged scan2+scan3: every block redundantly scans the <=128 block sums in
// smem, then applies the prefix to its 256 g_off entries.
__global__ __launch_bounds__(256) void k_scan23(int N, int nb, int E) {
    __shared__ int s[128];
    int t = threadIdx.x;
    if (t < 128) s[t] = (t < nb) ? g_bsum[t] : 0;
    __syncthreads();
#pragma unroll
    for (int o = 1; o < 128; o <<= 1) {
        int add = (t < 128 && t >= o) ? s[t - o] : 0;
        __syncthreads();
        if (t < 128) s[t] += add;
        __syncthreads();
    }
    int i = blockIdx.x * 256 + t;
    if (i < N) {
        int blk = i >> 10;
        int o = g_off[i] + (blk > 0 ? s[blk - 1] : 0);
        g_off[i] = o;
        g_cur[i] = o;
    }
    if (i == 0) g_off[N_NODES] = E;
}

__global__ void k_fill(const int* __restrict__ ei, const float* __restrict__ ew, int E) {
    int e = blockIdx.x * blockDim.x + threadIdx.x;
    if (e >= E) return;
    int src = __ldg(ei + e);
    int dst = __ldg(ei + E + e);
    int pos = atomicAdd(&g_cur[dst], 1);
    g_epack[pos] = ((ull)(unsigned)src << 32) | (ull)__float_as_uint(__ldg(ew + e));
}

// ---------------------------------------------------------------------------
// Gather (fp16 h) + fused epilogue: warp per dst, 4-way unroll.
// ---------------------------------------------------------------------------
__global__ __launch_bounds__(256) void gather_csr(const float* __restrict__ bias,
                                                  const float* __restrict__ pa,
                                                  float* __restrict__ out, int N) {
    int d    = (blockIdx.x * blockDim.x + threadIdx.x) >> 5;
    int lane = threadIdx.x & 31;
    if (d >= N) return;

    int beg = g_off[d];
    int end = g_off[d + 1];

    float4 a0 = make_float4(0.f, 0.f, 0.f, 0.f);
    float4 a1 = make_float4(0.f, 0.f, 0.f, 0.f);
    float4 a2 = make_float4(0.f, 0.f, 0.f, 0.f);
    float4 a3 = make_float4(0.f, 0.f, 0.f, 0.f);

    const __half* hp = g_hh;
    int i = beg;
    for (; i + 3 < end; i += 4) {
        ull p0 = __ldg(g_epack + i);
        ull p1 = __ldg(g_epack + i + 1);
        ull p2 = __ldg(g_epack + i + 2);
        ull p3 = __ldg(g_epack + i + 3);
        uint2 u0 = __ldg((const uint2*)(hp + (size_t)(p0 >> 32) * D + lane * 4));
        uint2 u1 = __ldg((const uint2*)(hp + (size_t)(p1 >> 32) * D + lane * 4));
        uint2 u2 = __ldg((const uint2*)(hp + (size_t)(p2 >> 32) * D + lane * 4));
        uint2 u3 = __ldg((const uint2*)(hp + (size_t)(p3 >> 32) * D + lane * 4));
        float w0 = __uint_as_float((unsigned)p0);
        float w1 = __uint_as_float((unsigned)p1);
        float w2 = __uint_as_float((unsigned)p2);
        float w3 = __uint_as_float((unsigned)p3);
        {
            float2 f0 = __half22float2(*(__half2*)&u0.x);
            float2 f1 = __half22float2(*(__half2*)&u0.y);
            a0.x += w0 * f0.x; a0.y += w0 * f0.y; a0.z += w0 * f1.x; a0.w += w0 * f1.y;
        }
        {
            float2 f0 = __half22float2(*(__half2*)&u1.x);
            float2 f1 = __half22float2(*(__half2*)&u1.y);
            a1.x += w1 * f0.x; a1.y += w1 * f0.y; a1.z += w1 * f1.x; a1.w += w1 * f1.y;
        }
        {
            float2 f0 = __half22float2(*(__half2*)&u2.x);
            float2 f1 = __half22float2(*(__half2*)&u2.y);
            a2.x += w2 * f0.x; a2.y += w2 * f0.y; a2.z += w2 * f1.x; a2.w += w2 * f1.y;
        }
        {
            float2 f0 = __half22float2(*(__half2*)&u3.x);
            float2 f1 = __half22float2(*(__half2*)&u3.y);
            a3.x += w3 * f0.x; a3.y += w3 * f0.y; a3.z += w3 * f1.x; a3.w += w3 * f1.y;
        }
    }
    for (; i < end; i++) {
        ull p0 = __ldg(g_epack + i);
        float w0 = __uint_as_float((unsigned)p0);
        uint2 u0 = __ldg((const uint2*)(hp + (size_t)(p0 >> 32) * D + lane * 4));
        float2 f0 = __half22float2(*(__half2*)&u0.x);
        float2 f1 = __half22float2(*(__half2*)&u0.y);
        a0.x += w0 * f0.x; a0.y += w0 * f0.y; a0.z += w0 * f1.x; a0.w += w0 * f1.y;
    }

    float  a = pa[0];
    float4 b = *(const float4*)(bias + lane * 4);
    float4 v;
    v.x = a0.x + a1.x + a2.x + a3.x + b.x;
    v.y = a0.y + a1.y + a2.y + a3.y + b.y;
    v.z = a0.z + a1.z + a2.z + a3.z + b.z;
    v.w = a0.w + a1.w + a2.w + a3.w + b.w;
    v.x = fmaxf(v.x >= 0.f ? v.x : a * v.x, 0.f);
    v.y = fmaxf(v.y >= 0.f ? v.y : a * v.y, 0.f);
    v.z = fmaxf(v.z >= 0.f ? v.z : a * v.z, 0.f);
    v.w = fmaxf(v.w >= 0.f ? v.w : a * v.w, 0.f);
    *(float4*)(out + (size_t)d * D + lane * 4) = v;
}

// ---------------------------------------------------------------------------
extern "C" void kernel_launch(void* const* d_in, const int* in_sizes, int n_in,
                              void* d_out, int out_size) {
    const float* x    = (const float*)d_in[0];
    const int*   ei   = (const int*)  d_in[1];
    const float* ew   = (const float*)d_in[2];
    const float* W    = (const float*)d_in[3];
    const float* bias = (const float*)d_in[4];
    const float* pa   = (const float*)d_in[5];
    float*       out  = (float*)d_out;

    const int N = in_sizes[0] / D;      // 100000
    const int E = in_sizes[2];          // 1600000
    const int nb = (N + 1023) / 1024;   // 98

    // zero histogram (memset node, no kernel)
    void* cnt_ptr = nullptr;
    cudaGetSymbolAddress(&cnt_ptr, g_cnt);
    cudaMemsetAsync(cnt_ptr, 0, (size_t)N * sizeof(int));

    // CSR build
    k_hist<<<(E + 255) / 256, 256>>>(ei, E);
    k_scan1<<<nb, 1024>>>(N);
    k_scan23<<<(N + 255) / 256, 256>>>(N, nb, E);
    k_fill<<<(E + 255) / 256, 256>>>(ei, ew, E);

    // h = x @ W^T on tensor cores (mma.sync tf32), fp16 output
    cudaFuncSetAttribute(gemm_mma, cudaFuncAttributeMaxDynamicSharedMemorySize, GEMM_SMEM);
    gemm_mma<<<(N + 127) / 128, 256, GEMM_SMEM>>>(x, W, N);

    // gather + bias + prelu + relu
    gather_csr<<<(N * 32 + 255) / 256, 256>>>(bias, pa, out, N);
}